// round 14
// baseline (speedup 1.0000x reference)
#include <cuda_runtime.h>
#include <cuda_fp16.h>
#include <cstdint>
#include <cstddef>

// Problem constants
#define B_   2
#define S_   1024
#define HID_ 2048
#define NH_  16
#define HD_  128
#define NN_  16
#define RHID_ 1024
#define SCALE_ 0.08838834764831845f   // 128^-0.5

// ---------------------------------------------------------------------------
// Scratch (device globals: allocation-free per harness rules)
// ---------------------------------------------------------------------------
__device__ __half g_qh  [4194304];     // (B*S, 2048) fp16
__device__ __half g_kvh [134217728];   // (B*S*NN, 4096): cols 0-2047 K, 2048-4095 V
__device__ __half g_aoh [4194304];     // attention output fp16

__device__ __half g_exth[33554432];    // ext fp16
__device__ __half g_hidh[4194304];     // hidden fp16
__device__ __half g_wqh [4194304];     // Wq^T fp16 (N x K)
__device__ __half g_wkvh[4194304];     // [Wk^T; Wv^T] (4096 x 1024)
__device__ __half g_woh [4194304];     // Wo^T

// ---------------------------------------------------------------------------
// PTX helpers (compute_103-safe: cp.async + ldmatrix + mma.sync only)
// ---------------------------------------------------------------------------
__device__ __forceinline__ void cp16(uint32_t dst, const void* src) {
    asm volatile("cp.async.cg.shared.global [%0], [%1], 16;"
                 :: "r"(dst), "l"(src) : "memory");
}

__device__ __forceinline__ void ldsm4(uint32_t* r, uint32_t a) {
    asm volatile("ldmatrix.sync.aligned.m8n8.x4.shared.b16 {%0,%1,%2,%3}, [%4];"
                 : "=r"(r[0]), "=r"(r[1]), "=r"(r[2]), "=r"(r[3]) : "r"(a));
}

__device__ __forceinline__ void mma_f16(float* c, const uint32_t* a,
                                        const uint32_t* b) {
    asm volatile(
        "mma.sync.aligned.m16n8k16.row.col.f32.f16.f16.f32 "
        "{%0,%1,%2,%3}, {%4,%5,%6,%7}, {%8,%9}, {%0,%1,%2,%3};"
        : "+f"(c[0]), "+f"(c[1]), "+f"(c[2]), "+f"(c[3])
        : "r"(a[0]), "r"(a[1]), "r"(a[2]), "r"(a[3]), "r"(b[0]), "r"(b[1]));
}

// Swizzled address for a 128-row x 64-byte tile packed 2-rows-per-128B line.
__device__ __forceinline__ uint32_t swz(uint32_t row, uint32_t cbyte) {
    uint32_t a = ((row >> 1) << 7) + ((row & 1) << 6) + cbyte;
    return a ^ (((row >> 1) & 7) << 4);
}

// ---------------------------------------------------------------------------
// fp16 tensor-core GEMM (R9 proven engine):
// C[M,N] = alpha * A[M,K] @ Bt[N,K]^T (+ R)
// CTA tile 128x128, BK=32, 256 threads (8 warps, 4x2), warp tile 32x64.
// 3-stage cp.async ring, one __syncthreads/K-block, 2 CTAs/SM.
// ---------------------------------------------------------------------------
#define GEMM_DSMEM 49152

template <bool HALF_OUT>
__global__ __launch_bounds__(256, 2) void gemm_mma_kernel(
    const __half* __restrict__ A, const __half* __restrict__ B,
    const float* __restrict__ R, void* __restrict__ Cv,
    int Kdim, int Ndim, float alpha)
{
    extern __shared__ __half sm[];
    const int tid = threadIdx.x;
    const int lane = tid & 31;
    const int wid = tid >> 5;
    const int wm = wid & 3;        // 4 warp-rows (m)
    const int wn = wid >> 2;       // 2 warp-cols (n)
    const int bm = blockIdx.y * 128;
    const int bn = blockIdx.x * 128;
    const int nkb = Kdim >> 5;     // BK = 32

    const uint32_t smem_b = (uint32_t)__cvta_generic_to_shared(sm);

    float acc[2][8][4];
#pragma unroll
    for (int mt = 0; mt < 2; mt++)
#pragma unroll
        for (int nt = 0; nt < 8; nt++)
#pragma unroll
            for (int i = 0; i < 4; i++) acc[mt][nt][i] = 0.f;

    auto load_stage = [&](int kb, int st) {
        if (kb < nkb) {
            const uint32_t base = smem_b + (uint32_t)st * 16384u;
#pragma unroll
            for (int i = 0; i < 4; i++) {
                const int t = i >> 1;                 // 0=A 1=B
                int cc = tid + (i & 1) * 256;         // 0..511 within tile
                int row = cc >> 2, u = cc & 3;
                const __half* p = (t == 0 ? A : B) +
                    (size_t)((t == 0 ? bm : bn) + row) * Kdim + kb * 32 + u * 8;
                cp16(base + (uint32_t)t * 8192u + swz((uint32_t)row,
                     (uint32_t)u * 16u), p);
            }
        }
        asm volatile("cp.async.commit_group;" ::: "memory");
    };

    uint32_t aoff[2], boff[4];
#pragma unroll
    for (int mt = 0; mt < 2; mt++)
        aoff[mt] = swz((uint32_t)(wm * 32 + mt * 16 + (lane & 7) +
                                  8 * ((lane >> 3) & 1)),
                       (uint32_t)(16 * (lane >> 4)));
#pragma unroll
    for (int np = 0; np < 4; np++)
        boff[np] = swz((uint32_t)(wn * 64 + np * 16 + (lane & 7) +
                                  8 * (lane >> 4)),
                       (uint32_t)(16 * ((lane >> 3) & 1)));

    load_stage(0, 0);
    load_stage(1, 1);

    int st = 0, st2 = 2;
    for (int kb = 0; kb < nkb; kb++) {
        asm volatile("cp.async.wait_group 1;" ::: "memory");
        __syncthreads();
        load_stage(kb + 2, st2);

        const uint32_t sA = smem_b + (uint32_t)st * 16384u;
        const uint32_t sB = sA + 8192u;

#pragma unroll
        for (int ks = 0; ks < 2; ks++) {
            const uint32_t kx = (uint32_t)(ks * 32);

            uint32_t ah[2][4];
#pragma unroll
            for (int mt = 0; mt < 2; mt++)
                ldsm4(ah[mt], sA + (aoff[mt] ^ kx));

            uint32_t bh[8][2];
#pragma unroll
            for (int np = 0; np < 4; np++) {
                uint32_t rh[4];
                ldsm4(rh, sB + (boff[np] ^ kx));
                bh[2 * np][0] = rh[0]; bh[2 * np][1] = rh[1];
                bh[2 * np + 1][0] = rh[2]; bh[2 * np + 1][1] = rh[3];
            }

#pragma unroll
            for (int mt = 0; mt < 2; mt++)
#pragma unroll
                for (int nt = 0; nt < 8; nt++)
                    mma_f16(acc[mt][nt], ah[mt], bh[nt]);
        }

        st  = (st  == 2) ? 0 : st + 1;
        st2 = (st2 == 2) ? 0 : st2 + 1;
    }

    // Epilogue
#pragma unroll
    for (int mt = 0; mt < 2; mt++) {
        int row0 = bm + wm * 32 + mt * 16 + (lane >> 2);
#pragma unroll
        for (int nt = 0; nt < 8; nt++) {
            int col = bn + wn * 64 + nt * 8 + 2 * (lane & 3);
            size_t i0 = (size_t)row0 * Ndim + col;
            size_t i1 = i0 + (size_t)8 * Ndim;
            if (HALF_OUT) {
                __half* C = (__half*)Cv;
                *(__half2*)(C + i0) = __floats2half2_rn(acc[mt][nt][0] * alpha,
                                                        acc[mt][nt][1] * alpha);
                *(__half2*)(C + i1) = __floats2half2_rn(acc[mt][nt][2] * alpha,
                                                        acc[mt][nt][3] * alpha);
            } else {
                float* C = (float*)Cv;
                float2 v0, v1;
                v0.x = acc[mt][nt][0] * alpha;
                v0.y = acc[mt][nt][1] * alpha;
                v1.x = acc[mt][nt][2] * alpha;
                v1.y = acc[mt][nt][3] * alpha;
                if (R) {
                    const float2 r0 = *(const float2*)(R + i0);
                    const float2 r1 = *(const float2*)(R + i1);
                    v0.x += r0.x; v0.y += r0.y;
                    v1.x += r1.x; v1.y += r1.y;
                }
                *(float2*)(C + i0) = v0;
                *(float2*)(C + i1) = v1;
            }
        }
    }
}

// ---------------------------------------------------------------------------
// fp32 -> fp16 convert (elementwise, float4)
// ---------------------------------------------------------------------------
__global__ __launch_bounds__(256) void cvt_kernel(
    const float* __restrict__ x, __half* __restrict__ h, int n4)
{
    int i = blockIdx.x * 256 + threadIdx.x;
    if (i >= n4) return;
    float4 v = ((const float4*)x)[i];
    ((__half2*)h)[2 * i]     = __floats2half2_rn(v.x, v.y);
    ((__half2*)h)[2 * i + 1] = __floats2half2_rn(v.z, v.w);
}

// ---------------------------------------------------------------------------
// Transpose + convert: W (K x N fp32) -> Wt (N x K fp16)
// ---------------------------------------------------------------------------
__global__ __launch_bounds__(256) void tcvt_kernel(
    const float* __restrict__ W, __half* __restrict__ h, int K, int N)
{
    __shared__ float t[32][33];
    const int tx = threadIdx.x, ty = threadIdx.y;  // 32 x 8
    const int bn = blockIdx.x * 32;
    const int bk = blockIdx.y * 32;
#pragma unroll
    for (int r = 0; r < 4; r++)
        t[ty + r * 8][tx] = W[(size_t)(bk + ty + r * 8) * N + bn + tx];
    __syncthreads();
#pragma unroll
    for (int r = 0; r < 4; r++) {
        int row = ty + r * 8;
        h[(size_t)(bn + row) * K + bk + tx] = __float2half_rn(t[tx][row]);
    }
}

// ---------------------------------------------------------------------------
// Attention — fp16 Q + combined KV (4096-wide: K cols 0-2047, V 2048-4095).
// Per (b,s,h) block of 128 threads.
// ---------------------------------------------------------------------------
__global__ __launch_bounds__(128) void attn_kernel(
    const __half* __restrict__ qb, const __half* __restrict__ kvb,
    __half* __restrict__ ob)
{
    const int h = blockIdx.x;
    const int s = blockIdx.y;
    const int b = blockIdx.z;
    const int tid = threadIdx.x;
    const int lane = tid & 31;
    const int w = tid >> 5;

    __shared__ float sc[32];
    __shared__ float pr[32];

    const __half* qv = qb + ((size_t)(b * S_ + s) * NH_ + h) * HD_;
    float2 qraw = ((const float2*)qv)[lane];
    __half2 q01 = *(__half2*)&qraw.x;
    __half2 q23 = *(__half2*)&qraw.y;
    float2 qf0 = __half22float2(q01);
    float2 qf1 = __half22float2(q23);

    const int pprev = (s > 0) ? (s - 1) : 0;

#pragma unroll
    for (int j = 0; j < 8; j++) {
        int i = w * 8 + j;
        int p = (i < 16) ? pprev : s;
        int n = i & 15;
        const __half* kr = kvb + ((size_t)((b * S_ + p) * NN_ + h)) * 4096 + n * HD_;
        float2 kraw = ((const float2*)kr)[lane];
        __half2 k01 = *(__half2*)&kraw.x;
        __half2 k23 = *(__half2*)&kraw.y;
        float2 kf0 = __half22float2(k01);
        float2 kf1 = __half22float2(k23);
        float part = qf0.x * kf0.x + qf0.y * kf0.y + qf1.x * kf1.x + qf1.y * kf1.y;
#pragma unroll
        for (int off = 16; off; off >>= 1)
            part += __shfl_xor_sync(0xffffffffu, part, off);
        if (lane == 0) sc[i] = part;
    }
    __syncthreads();

    if (tid < 32) {
        float x = sc[tid];
        float m = x;
#pragma unroll
        for (int off = 16; off; off >>= 1)
            m = fmaxf(m, __shfl_xor_sync(0xffffffffu, m, off));
        float e = expf(x - m);
        float sum = e;
#pragma unroll
        for (int off = 16; off; off >>= 1)
            sum += __shfl_xor_sync(0xffffffffu, sum, off);
        pr[tid] = e / sum;
    }
    __syncthreads();

    float acc = 0.f;
    const int d = tid;
#pragma unroll 8
    for (int i = 0; i < 32; i++) {
        int p = (i < 16) ? pprev : s;
        int n = i & 15;
        acc += pr[i] * __half2float(
            kvb[((size_t)((b * S_ + p) * NN_ + h)) * 4096 + 2048 + n * HD_ + d]);
    }
    ob[((size_t)(b * S_ + s) * NH_ + h) * HD_ + d] = __float2half_rn(acc);
}

// ---------------------------------------------------------------------------
// Launch — multi-stream DAG:
//   sA: ext cvt in 4 M-chunks (events eC[0..3])
//   sB: Wk/Wv tcvt -> merged KV GEMM in 4 M-chunks (each waits eC[c]) -> eKV
//   s2: hidden cvt -> Wq tcvt -> Q GEMM -> Wo tcvt -> eQ
//   0:  join (eKV, eQ) -> attention -> O GEMM
// ---------------------------------------------------------------------------
extern "C" void kernel_launch(void* const* d_in, const int* in_sizes, int n_in,
                              void* d_out, int out_size)
{
    const float* hidden = (const float*)d_in[0];  // (B,S,HID)
    const float* ext    = (const float*)d_in[1];  // (B,S,NN,RHID)
    const float* Wq     = (const float*)d_in[2];  // (HID, 2048)
    const float* Wk     = (const float*)d_in[3];  // (RHID, 2048)
    const float* Wv     = (const float*)d_in[4];  // (RHID, 2048)
    const float* Wo     = (const float*)d_in[5];  // (2048, HID)
    float* out = (float*)d_out;

    __half *qh, *kvh, *aoh, *exth, *hidh, *wqh, *wkvh, *woh;
    cudaGetSymbolAddress((void**)&qh,   g_qh);
    cudaGetSymbolAddress((void**)&kvh,  g_kvh);
    cudaGetSymbolAddress((void**)&aoh,  g_aoh);
    cudaGetSymbolAddress((void**)&exth, g_exth);
    cudaGetSymbolAddress((void**)&hidh, g_hidh);
    cudaGetSymbolAddress((void**)&wqh,  g_wqh);
    cudaGetSymbolAddress((void**)&wkvh, g_wkvh);
    cudaGetSymbolAddress((void**)&woh,  g_woh);

    cudaFuncSetAttribute(gemm_mma_kernel<true>,
                         cudaFuncAttributeMaxDynamicSharedMemorySize, GEMM_DSMEM);
    cudaFuncSetAttribute(gemm_mma_kernel<false>,
                         cudaFuncAttributeMaxDynamicSharedMemorySize, GEMM_DSMEM);

    // One-time host-object creation (no device memory).
    static cudaStream_t sA = nullptr, sB = nullptr, s2 = nullptr;
    static cudaEvent_t eFork = nullptr, eC[4], eKV = nullptr, eQ = nullptr;
    if (sA == nullptr) {
        cudaStreamCreateWithFlags(&sA, cudaStreamNonBlocking);
        cudaStreamCreateWithFlags(&sB, cudaStreamNonBlocking);
        cudaStreamCreateWithFlags(&s2, cudaStreamNonBlocking);
        cudaEventCreateWithFlags(&eFork, cudaEventDisableTiming);
        for (int c = 0; c < 4; c++)
            cudaEventCreateWithFlags(&eC[c], cudaEventDisableTiming);
        cudaEventCreateWithFlags(&eKV, cudaEventDisableTiming);
        cudaEventCreateWithFlags(&eQ, cudaEventDisableTiming);
    }

    cudaEventRecord(eFork, 0);
    cudaStreamWaitEvent(sA, eFork, 0);
    cudaStreamWaitEvent(sB, eFork, 0);
    cudaStreamWaitEvent(s2, eFork, 0);

    // --- sA: ext convert in 4 chunks of 8192 rows (2,097,152 float4 each)
    for (int c = 0; c < 4; c++) {
        const float* src = ext + (size_t)c * 8192 * 1024;
        __half* dst = exth + (size_t)c * 8192 * 1024;
        cvt_kernel<<<8192, 256, 0, sA>>>(src, dst, 2097152);
        cudaEventRecord(eC[c], sA);
    }

    // --- sB: combined weights, then chunked merged KV GEMM (N=4096)
    tcvt_kernel<<<dim3(64, 32), dim3(32, 8), 0, sB>>>(Wk, wkvh, 1024, 2048);
    tcvt_kernel<<<dim3(64, 32), dim3(32, 8), 0, sB>>>(Wv, wkvh + (size_t)2048 * 1024,
                                                      1024, 2048);
    for (int c = 0; c < 4; c++) {
        cudaStreamWaitEvent(sB, eC[c], 0);
        const __half* Ac = exth + (size_t)c * 8192 * 1024;
        __half* Cc = kvh + (size_t)c * 8192 * 4096;
        gemm_mma_kernel<true><<<dim3(32, 64), 256, GEMM_DSMEM, sB>>>(
            Ac, wkvh, nullptr, Cc, 1024, 4096, 1.0f);
    }
    cudaEventRecord(eKV, sB);

    // --- s2: Q chain + Wo prep
    cvt_kernel<<<4096, 256, 0, s2>>>(hidden, hidh, 1048576);
    tcvt_kernel<<<dim3(64, 64), dim3(32, 8), 0, s2>>>(Wq, wqh, 2048, 2048);
    gemm_mma_kernel<true><<<dim3(16, 16), 256, GEMM_DSMEM, s2>>>(
        hidh, wqh, nullptr, qh, 2048, 2048, SCALE_);
    tcvt_kernel<<<dim3(64, 64), dim3(32, 8), 0, s2>>>(Wo, woh, 2048, 2048);
    cudaEventRecord(eQ, s2);

    // --- default stream: join, attention, output projection
    cudaStreamWaitEvent(0, eKV, 0);
    cudaStreamWaitEvent(0, eQ, 0);
    attn_kernel<<<dim3(NH_, S_, B_), dim3(128)>>>(qh, kvh, aoh);
    gemm_mma_kernel<false><<<dim3(16, 16), 256, GEMM_DSMEM>>>(
        aoh, woh, hidden, out, 2048, 2048, 1.0f);
}

// round 15
// speedup vs baseline: 1.0303x; 1.0303x over previous
#include <cuda_runtime.h>
#include <cuda_fp16.h>
#include <cstdint>
#include <cstddef>

// Problem constants
#define B_   2
#define S_   1024
#define HID_ 2048
#define NH_  16
#define HD_  128
#define NN_  16
#define RHID_ 1024
#define SCALE_ 0.08838834764831845f   // 128^-0.5

// ---------------------------------------------------------------------------
// Scratch (device globals: allocation-free per harness rules)
// ---------------------------------------------------------------------------
__device__ __half g_qh  [4194304];     // (B*S, 2048) fp16
__device__ __half g_kvh [134217728];   // (B*S*NN, 4096): cols 0-2047 K, 2048-4095 V
__device__ __half g_aoh [4194304];     // attention output fp16

__device__ __half g_exth[33554432];    // ext fp16
__device__ __half g_hidh[4194304];     // hidden fp16
__device__ __half g_wqh [4194304];     // Wq^T fp16 (N x K)
__device__ __half g_wkvh[4194304];     // [Wk^T; Wv^T] (4096 x 1024)
__device__ __half g_woh [4194304];     // Wo^T

// ---------------------------------------------------------------------------
// PTX helpers (compute_103-safe: cp.async + ldmatrix + mma.sync only)
// ---------------------------------------------------------------------------
__device__ __forceinline__ void cp16(uint32_t dst, const void* src) {
    asm volatile("cp.async.cg.shared.global [%0], [%1], 16;"
                 :: "r"(dst), "l"(src) : "memory");
}

__device__ __forceinline__ void ldsm4(uint32_t* r, uint32_t a) {
    asm volatile("ldmatrix.sync.aligned.m8n8.x4.shared.b16 {%0,%1,%2,%3}, [%4];"
                 : "=r"(r[0]), "=r"(r[1]), "=r"(r[2]), "=r"(r[3]) : "r"(a));
}

__device__ __forceinline__ void mma_f16(float* c, const uint32_t* a,
                                        const uint32_t* b) {
    asm volatile(
        "mma.sync.aligned.m16n8k16.row.col.f32.f16.f16.f32 "
        "{%0,%1,%2,%3}, {%4,%5,%6,%7}, {%8,%9}, {%0,%1,%2,%3};"
        : "+f"(c[0]), "+f"(c[1]), "+f"(c[2]), "+f"(c[3])
        : "r"(a[0]), "r"(a[1]), "r"(a[2]), "r"(a[3]), "r"(b[0]), "r"(b[1]));
}

// Swizzled address for a 128-row x 64-byte tile packed 2-rows-per-128B line.
__device__ __forceinline__ uint32_t swz(uint32_t row, uint32_t cbyte) {
    uint32_t a = ((row >> 1) << 7) + ((row & 1) << 6) + cbyte;
    return a ^ (((row >> 1) & 7) << 4);
}

// ---------------------------------------------------------------------------
// fp16 tensor-core GEMM (R9 proven engine):
// C[M,N] = alpha * A[M,K] @ Bt[N,K]^T (+ R)
// CTA tile 128x128, BK=32, 256 threads (8 warps, 4x2), warp tile 32x64.
// 3-stage cp.async ring, one __syncthreads/K-block, 2 CTAs/SM.
// ---------------------------------------------------------------------------
#define GEMM_DSMEM 49152

template <bool HALF_OUT>
__global__ __launch_bounds__(256, 2) void gemm_mma_kernel(
    const __half* __restrict__ A, const __half* __restrict__ B,
    const float* __restrict__ R, void* __restrict__ Cv,
    int Kdim, int Ndim, float alpha)
{
    extern __shared__ __half sm[];
    const int tid = threadIdx.x;
    const int lane = tid & 31;
    const int wid = tid >> 5;
    const int wm = wid & 3;        // 4 warp-rows (m)
    const int wn = wid >> 2;       // 2 warp-cols (n)
    const int bm = blockIdx.y * 128;
    const int bn = blockIdx.x * 128;
    const int nkb = Kdim >> 5;     // BK = 32

    const uint32_t smem_b = (uint32_t)__cvta_generic_to_shared(sm);

    float acc[2][8][4];
#pragma unroll
    for (int mt = 0; mt < 2; mt++)
#pragma unroll
        for (int nt = 0; nt < 8; nt++)
#pragma unroll
            for (int i = 0; i < 4; i++) acc[mt][nt][i] = 0.f;

    auto load_stage = [&](int kb, int st) {
        if (kb < nkb) {
            const uint32_t base = smem_b + (uint32_t)st * 16384u;
#pragma unroll
            for (int i = 0; i < 4; i++) {
                const int t = i >> 1;                 // 0=A 1=B
                int cc = tid + (i & 1) * 256;         // 0..511 within tile
                int row = cc >> 2, u = cc & 3;
                const __half* p = (t == 0 ? A : B) +
                    (size_t)((t == 0 ? bm : bn) + row) * Kdim + kb * 32 + u * 8;
                cp16(base + (uint32_t)t * 8192u + swz((uint32_t)row,
                     (uint32_t)u * 16u), p);
            }
        }
        asm volatile("cp.async.commit_group;" ::: "memory");
    };

    uint32_t aoff[2], boff[4];
#pragma unroll
    for (int mt = 0; mt < 2; mt++)
        aoff[mt] = swz((uint32_t)(wm * 32 + mt * 16 + (lane & 7) +
                                  8 * ((lane >> 3) & 1)),
                       (uint32_t)(16 * (lane >> 4)));
#pragma unroll
    for (int np = 0; np < 4; np++)
        boff[np] = swz((uint32_t)(wn * 64 + np * 16 + (lane & 7) +
                                  8 * (lane >> 4)),
                       (uint32_t)(16 * ((lane >> 3) & 1)));

    load_stage(0, 0);
    load_stage(1, 1);

    int st = 0, st2 = 2;
    for (int kb = 0; kb < nkb; kb++) {
        asm volatile("cp.async.wait_group 1;" ::: "memory");
        __syncthreads();
        load_stage(kb + 2, st2);

        const uint32_t sA = smem_b + (uint32_t)st * 16384u;
        const uint32_t sB = sA + 8192u;

#pragma unroll
        for (int ks = 0; ks < 2; ks++) {
            const uint32_t kx = (uint32_t)(ks * 32);

            uint32_t ah[2][4];
#pragma unroll
            for (int mt = 0; mt < 2; mt++)
                ldsm4(ah[mt], sA + (aoff[mt] ^ kx));

            uint32_t bh[8][2];
#pragma unroll
            for (int np = 0; np < 4; np++) {
                uint32_t rh[4];
                ldsm4(rh, sB + (boff[np] ^ kx));
                bh[2 * np][0] = rh[0]; bh[2 * np][1] = rh[1];
                bh[2 * np + 1][0] = rh[2]; bh[2 * np + 1][1] = rh[3];
            }

#pragma unroll
            for (int mt = 0; mt < 2; mt++)
#pragma unroll
                for (int nt = 0; nt < 8; nt++)
                    mma_f16(acc[mt][nt], ah[mt], bh[nt]);
        }

        st  = (st  == 2) ? 0 : st + 1;
        st2 = (st2 == 2) ? 0 : st2 + 1;
    }

    // Epilogue
#pragma unroll
    for (int mt = 0; mt < 2; mt++) {
        int row0 = bm + wm * 32 + mt * 16 + (lane >> 2);
#pragma unroll
        for (int nt = 0; nt < 8; nt++) {
            int col = bn + wn * 64 + nt * 8 + 2 * (lane & 3);
            size_t i0 = (size_t)row0 * Ndim + col;
            size_t i1 = i0 + (size_t)8 * Ndim;
            if (HALF_OUT) {
                __half* C = (__half*)Cv;
                *(__half2*)(C + i0) = __floats2half2_rn(acc[mt][nt][0] * alpha,
                                                        acc[mt][nt][1] * alpha);
                *(__half2*)(C + i1) = __floats2half2_rn(acc[mt][nt][2] * alpha,
                                                        acc[mt][nt][3] * alpha);
            } else {
                float* C = (float*)Cv;
                float2 v0, v1;
                v0.x = acc[mt][nt][0] * alpha;
                v0.y = acc[mt][nt][1] * alpha;
                v1.x = acc[mt][nt][2] * alpha;
                v1.y = acc[mt][nt][3] * alpha;
                if (R) {
                    const float2 r0 = *(const float2*)(R + i0);
                    const float2 r1 = *(const float2*)(R + i1);
                    v0.x += r0.x; v0.y += r0.y;
                    v1.x += r1.x; v1.y += r1.y;
                }
                *(float2*)(C + i0) = v0;
                *(float2*)(C + i1) = v1;
            }
        }
    }
}

// ---------------------------------------------------------------------------
// fp32 -> fp16 convert (elementwise, float4)
// ---------------------------------------------------------------------------
__global__ __launch_bounds__(256) void cvt_kernel(
    const float* __restrict__ x, __half* __restrict__ h, int n4)
{
    int i = blockIdx.x * 256 + threadIdx.x;
    if (i >= n4) return;
    float4 v = ((const float4*)x)[i];
    ((__half2*)h)[2 * i]     = __floats2half2_rn(v.x, v.y);
    ((__half2*)h)[2 * i + 1] = __floats2half2_rn(v.z, v.w);
}

// ---------------------------------------------------------------------------
// Transpose + convert: W (K x N fp32) -> Wt (N x K fp16)
// ---------------------------------------------------------------------------
__global__ __launch_bounds__(256) void tcvt_kernel(
    const float* __restrict__ W, __half* __restrict__ h, int K, int N)
{
    __shared__ float t[32][33];
    const int tx = threadIdx.x, ty = threadIdx.y;  // 32 x 8
    const int bn = blockIdx.x * 32;
    const int bk = blockIdx.y * 32;
#pragma unroll
    for (int r = 0; r < 4; r++)
        t[ty + r * 8][tx] = W[(size_t)(bk + ty + r * 8) * N + bn + tx];
    __syncthreads();
#pragma unroll
    for (int r = 0; r < 4; r++) {
        int row = ty + r * 8;
        h[(size_t)(bn + row) * K + bk + tx] = __float2half_rn(t[tx][row]);
    }
}

// ---------------------------------------------------------------------------
// Attention — fp16 Q + combined KV (4096-wide: K cols 0-2047, V 2048-4095).
// Per (b0+blockIdx.z, s, h) block of 128 threads; b0 selects batch chunk.
// ---------------------------------------------------------------------------
__global__ __launch_bounds__(128) void attn_kernel(
    const __half* __restrict__ qb, const __half* __restrict__ kvb,
    __half* __restrict__ ob, int b0)
{
    const int h = blockIdx.x;
    const int s = blockIdx.y;
    const int b = b0 + blockIdx.z;
    const int tid = threadIdx.x;
    const int lane = tid & 31;
    const int w = tid >> 5;

    __shared__ float sc[32];
    __shared__ float pr[32];

    const __half* qv = qb + ((size_t)(b * S_ + s) * NH_ + h) * HD_;
    float2 qraw = ((const float2*)qv)[lane];
    __half2 q01 = *(__half2*)&qraw.x;
    __half2 q23 = *(__half2*)&qraw.y;
    float2 qf0 = __half22float2(q01);
    float2 qf1 = __half22float2(q23);

    const int pprev = (s > 0) ? (s - 1) : 0;

#pragma unroll
    for (int j = 0; j < 8; j++) {
        int i = w * 8 + j;
        int p = (i < 16) ? pprev : s;
        int n = i & 15;
        const __half* kr = kvb + ((size_t)((b * S_ + p) * NN_ + h)) * 4096 + n * HD_;
        float2 kraw = ((const float2*)kr)[lane];
        __half2 k01 = *(__half2*)&kraw.x;
        __half2 k23 = *(__half2*)&kraw.y;
        float2 kf0 = __half22float2(k01);
        float2 kf1 = __half22float2(k23);
        float part = qf0.x * kf0.x + qf0.y * kf0.y + qf1.x * kf1.x + qf1.y * kf1.y;
#pragma unroll
        for (int off = 16; off; off >>= 1)
            part += __shfl_xor_sync(0xffffffffu, part, off);
        if (lane == 0) sc[i] = part;
    }
    __syncthreads();

    if (tid < 32) {
        float x = sc[tid];
        float m = x;
#pragma unroll
        for (int off = 16; off; off >>= 1)
            m = fmaxf(m, __shfl_xor_sync(0xffffffffu, m, off));
        float e = expf(x - m);
        float sum = e;
#pragma unroll
        for (int off = 16; off; off >>= 1)
            sum += __shfl_xor_sync(0xffffffffu, sum, off);
        pr[tid] = e / sum;
    }
    __syncthreads();

    float acc = 0.f;
    const int d = tid;
#pragma unroll 8
    for (int i = 0; i < 32; i++) {
        int p = (i < 16) ? pprev : s;
        int n = i & 15;
        acc += pr[i] * __half2float(
            kvb[((size_t)((b * S_ + p) * NN_ + h)) * 4096 + 2048 + n * HD_ + d]);
    }
    ob[((size_t)(b * S_ + s) * NH_ + h) * HD_ + d] = __float2half_rn(acc);
}

// ---------------------------------------------------------------------------
// Launch — DAG:
//   0 (default): ext cvt -> Wk/Wv tcvt -> merged KV GEMM (one launch) -> eKV
//   s2:          hidden cvt -> Wq tcvt -> Q GEMM -> Wo tcvt -> eQ
//   join; then batch-split tail:
//   0:  attn(b=0) -> eA0 ; attn(b=1) ; O GEMM rows 1024-2047
//   s2: wait eA0 ; O GEMM rows 0-1023 -> eO0 ; 0 waits eO0.
// ---------------------------------------------------------------------------
extern "C" void kernel_launch(void* const* d_in, const int* in_sizes, int n_in,
                              void* d_out, int out_size)
{
    const float* hidden = (const float*)d_in[0];  // (B,S,HID)
    const float* ext    = (const float*)d_in[1];  // (B,S,NN,RHID)
    const float* Wq     = (const float*)d_in[2];  // (HID, 2048)
    const float* Wk     = (const float*)d_in[3];  // (RHID, 2048)
    const float* Wv     = (const float*)d_in[4];  // (RHID, 2048)
    const float* Wo     = (const float*)d_in[5];  // (2048, HID)
    float* out = (float*)d_out;

    __half *qh, *kvh, *aoh, *exth, *hidh, *wqh, *wkvh, *woh;
    cudaGetSymbolAddress((void**)&qh,   g_qh);
    cudaGetSymbolAddress((void**)&kvh,  g_kvh);
    cudaGetSymbolAddress((void**)&aoh,  g_aoh);
    cudaGetSymbolAddress((void**)&exth, g_exth);
    cudaGetSymbolAddress((void**)&hidh, g_hidh);
    cudaGetSymbolAddress((void**)&wqh,  g_wqh);
    cudaGetSymbolAddress((void**)&wkvh, g_wkvh);
    cudaGetSymbolAddress((void**)&woh,  g_woh);

    cudaFuncSetAttribute(gemm_mma_kernel<true>,
                         cudaFuncAttributeMaxDynamicSharedMemorySize, GEMM_DSMEM);
    cudaFuncSetAttribute(gemm_mma_kernel<false>,
                         cudaFuncAttributeMaxDynamicSharedMemorySize, GEMM_DSMEM);

    // One-time host-object creation (no device memory).
    static cudaStream_t s2 = nullptr;
    static cudaEvent_t eFork = nullptr, eKV = nullptr, eQ = nullptr,
                       eA0 = nullptr, eO0 = nullptr;
    if (s2 == nullptr) {
        cudaStreamCreateWithFlags(&s2, cudaStreamNonBlocking);
        cudaEventCreateWithFlags(&eFork, cudaEventDisableTiming);
        cudaEventCreateWithFlags(&eKV, cudaEventDisableTiming);
        cudaEventCreateWithFlags(&eQ, cudaEventDisableTiming);
        cudaEventCreateWithFlags(&eA0, cudaEventDisableTiming);
        cudaEventCreateWithFlags(&eO0, cudaEventDisableTiming);
    }

    cudaEventRecord(eFork, 0);
    cudaStreamWaitEvent(s2, eFork, 0);

    // --- s2: Q chain + Wo prep (independent of ext/KV) ---
    cvt_kernel<<<4096, 256, 0, s2>>>(hidden, hidh, 1048576);
    tcvt_kernel<<<dim3(64, 64), dim3(32, 8), 0, s2>>>(Wq, wqh, 2048, 2048);
    gemm_mma_kernel<true><<<dim3(16, 16), 256, GEMM_DSMEM, s2>>>(
        hidh, wqh, nullptr, qh, 2048, 2048, SCALE_);
    tcvt_kernel<<<dim3(64, 64), dim3(32, 8), 0, s2>>>(Wo, woh, 2048, 2048);
    cudaEventRecord(eQ, s2);

    // --- default stream: ext cvt -> merged KV GEMM (single launch) ---
    cvt_kernel<<<32768, 256>>>(ext, exth, 8388608);
    tcvt_kernel<<<dim3(64, 32), dim3(32, 8)>>>(Wk, wkvh, 1024, 2048);
    tcvt_kernel<<<dim3(64, 32), dim3(32, 8)>>>(Wv, wkvh + (size_t)2048 * 1024,
                                               1024, 2048);
    gemm_mma_kernel<true><<<dim3(32, 256), 256, GEMM_DSMEM>>>(
        exth, wkvh, nullptr, kvh, 1024, 4096, 1.0f);

    // --- join Q chain, then batch-split attention + O projection ---
    cudaStreamWaitEvent(0, eQ, 0);
    attn_kernel<<<dim3(NH_, S_, 1), dim3(128)>>>(qh, kvh, aoh, 0);   // batch 0
    cudaEventRecord(eA0, 0);
    attn_kernel<<<dim3(NH_, S_, 1), dim3(128)>>>(qh, kvh, aoh, 1);   // batch 1

    // s2: O GEMM for batch-0 rows [0,1024) as soon as attn(b=0) is done
    cudaStreamWaitEvent(s2, eA0, 0);
    gemm_mma_kernel<false><<<dim3(16, 8), 256, GEMM_DSMEM, s2>>>(
        aoh, woh, hidden, out, 2048, 2048, 1.0f);
    cudaEventRecord(eO0, s2);

    // default: O GEMM for batch-1 rows [1024,2048)
    gemm_mma_kernel<false><<<dim3(16, 8), 256, GEMM_DSMEM>>>(
        aoh + (size_t)1024 * 2048, woh, hidden + (size_t)1024 * 2048,
        out + (size_t)1024 * 2048, 2048, 2048, 1.0f);

    // join s2 back into the origin stream before returning
    cudaStreamWaitEvent(0, eO0, 0);
}

// round 16
// speedup vs baseline: 1.0309x; 1.0006x over previous
#include <cuda_runtime.h>
#include <cuda_fp16.h>
#include <cstdint>
#include <cstddef>

// Problem constants
#define B_   2
#define S_   1024
#define HID_ 2048
#define NH_  16
#define HD_  128
#define NN_  16
#define RHID_ 1024
#define SCALE_ 0.08838834764831845f   // 128^-0.5

// ---------------------------------------------------------------------------
// Scratch (device globals: allocation-free per harness rules)
// ---------------------------------------------------------------------------
__device__ __half g_qh  [4194304];     // (B*S, 2048) fp16
__device__ __half g_kvh [134217728];   // (B*S*NN, 4096): cols 0-2047 K, 2048-4095 V
__device__ __half g_aoh [4194304];     // attention output fp16

__device__ __half g_exth[33554432];    // ext fp16
__device__ __half g_hidh[4194304];     // hidden fp16
__device__ __half g_wqh [4194304];     // Wq^T fp16 (N x K)
__device__ __half g_wkvh[4194304];     // [Wk^T; Wv^T] (4096 x 1024)
__device__ __half g_woh [4194304];     // Wo^T

// ---------------------------------------------------------------------------
// PTX helpers (compute_103-safe: cp.async + ldmatrix + mma.sync only)
// ---------------------------------------------------------------------------
__device__ __forceinline__ void cp16(uint32_t dst, const void* src) {
    asm volatile("cp.async.cg.shared.global [%0], [%1], 16;"
                 :: "r"(dst), "l"(src) : "memory");
}

__device__ __forceinline__ void ldsm4(uint32_t* r, uint32_t a) {
    asm volatile("ldmatrix.sync.aligned.m8n8.x4.shared.b16 {%0,%1,%2,%3}, [%4];"
                 : "=r"(r[0]), "=r"(r[1]), "=r"(r[2]), "=r"(r[3]) : "r"(a));
}

__device__ __forceinline__ void mma_f16(float* c, const uint32_t* a,
                                        const uint32_t* b) {
    asm volatile(
        "mma.sync.aligned.m16n8k16.row.col.f32.f16.f16.f32 "
        "{%0,%1,%2,%3}, {%4,%5,%6,%7}, {%8,%9}, {%0,%1,%2,%3};"
        : "+f"(c[0]), "+f"(c[1]), "+f"(c[2]), "+f"(c[3])
        : "r"(a[0]), "r"(a[1]), "r"(a[2]), "r"(a[3]), "r"(b[0]), "r"(b[1]));
}

// Swizzled address for a 128-row x 64-byte tile packed 2-rows-per-128B line.
__device__ __forceinline__ uint32_t swz(uint32_t row, uint32_t cbyte) {
    uint32_t a = ((row >> 1) << 7) + ((row & 1) << 6) + cbyte;
    return a ^ (((row >> 1) & 7) << 4);
}

// ---------------------------------------------------------------------------
// fp16 tensor-core GEMM (R9 proven engine):
// C[M,N] = alpha * A[M,K] @ Bt[N,K]^T (+ R)
// CTA tile 128x128, BK=32, 256 threads (8 warps, 4x2), warp tile 32x64.
// 3-stage cp.async ring, one __syncthreads/K-block, 2 CTAs/SM.
// ---------------------------------------------------------------------------
#define GEMM_DSMEM 49152

template <bool HALF_OUT>
__global__ __launch_bounds__(256, 2) void gemm_mma_kernel(
    const __half* __restrict__ A, const __half* __restrict__ B,
    const float* __restrict__ R, void* __restrict__ Cv,
    int Kdim, int Ndim, float alpha)
{
    extern __shared__ __half sm[];
    const int tid = threadIdx.x;
    const int lane = tid & 31;
    const int wid = tid >> 5;
    const int wm = wid & 3;        // 4 warp-rows (m)
    const int wn = wid >> 2;       // 2 warp-cols (n)
    const int bm = blockIdx.y * 128;
    const int bn = blockIdx.x * 128;
    const int nkb = Kdim >> 5;     // BK = 32

    const uint32_t smem_b = (uint32_t)__cvta_generic_to_shared(sm);

    float acc[2][8][4];
#pragma unroll
    for (int mt = 0; mt < 2; mt++)
#pragma unroll
        for (int nt = 0; nt < 8; nt++)
#pragma unroll
            for (int i = 0; i < 4; i++) acc[mt][nt][i] = 0.f;

    auto load_stage = [&](int kb, int st) {
        if (kb < nkb) {
            const uint32_t base = smem_b + (uint32_t)st * 16384u;
#pragma unroll
            for (int i = 0; i < 4; i++) {
                const int t = i >> 1;                 // 0=A 1=B
                int cc = tid + (i & 1) * 256;         // 0..511 within tile
                int row = cc >> 2, u = cc & 3;
                const __half* p = (t == 0 ? A : B) +
                    (size_t)((t == 0 ? bm : bn) + row) * Kdim + kb * 32 + u * 8;
                cp16(base + (uint32_t)t * 8192u + swz((uint32_t)row,
                     (uint32_t)u * 16u), p);
            }
        }
        asm volatile("cp.async.commit_group;" ::: "memory");
    };

    uint32_t aoff[2], boff[4];
#pragma unroll
    for (int mt = 0; mt < 2; mt++)
        aoff[mt] = swz((uint32_t)(wm * 32 + mt * 16 + (lane & 7) +
                                  8 * ((lane >> 3) & 1)),
                       (uint32_t)(16 * (lane >> 4)));
#pragma unroll
    for (int np = 0; np < 4; np++)
        boff[np] = swz((uint32_t)(wn * 64 + np * 16 + (lane & 7) +
                                  8 * (lane >> 4)),
                       (uint32_t)(16 * ((lane >> 3) & 1)));

    load_stage(0, 0);
    load_stage(1, 1);

    int st = 0, st2 = 2;
    for (int kb = 0; kb < nkb; kb++) {
        asm volatile("cp.async.wait_group 1;" ::: "memory");
        __syncthreads();
        load_stage(kb + 2, st2);

        const uint32_t sA = smem_b + (uint32_t)st * 16384u;
        const uint32_t sB = sA + 8192u;

#pragma unroll
        for (int ks = 0; ks < 2; ks++) {
            const uint32_t kx = (uint32_t)(ks * 32);

            uint32_t ah[2][4];
#pragma unroll
            for (int mt = 0; mt < 2; mt++)
                ldsm4(ah[mt], sA + (aoff[mt] ^ kx));

            uint32_t bh[8][2];
#pragma unroll
            for (int np = 0; np < 4; np++) {
                uint32_t rh[4];
                ldsm4(rh, sB + (boff[np] ^ kx));
                bh[2 * np][0] = rh[0]; bh[2 * np][1] = rh[1];
                bh[2 * np + 1][0] = rh[2]; bh[2 * np + 1][1] = rh[3];
            }

#pragma unroll
            for (int mt = 0; mt < 2; mt++)
#pragma unroll
                for (int nt = 0; nt < 8; nt++)
                    mma_f16(acc[mt][nt], ah[mt], bh[nt]);
        }

        st  = (st  == 2) ? 0 : st + 1;
        st2 = (st2 == 2) ? 0 : st2 + 1;
    }

    // Epilogue
#pragma unroll
    for (int mt = 0; mt < 2; mt++) {
        int row0 = bm + wm * 32 + mt * 16 + (lane >> 2);
#pragma unroll
        for (int nt = 0; nt < 8; nt++) {
            int col = bn + wn * 64 + nt * 8 + 2 * (lane & 3);
            size_t i0 = (size_t)row0 * Ndim + col;
            size_t i1 = i0 + (size_t)8 * Ndim;
            if (HALF_OUT) {
                __half* C = (__half*)Cv;
                *(__half2*)(C + i0) = __floats2half2_rn(acc[mt][nt][0] * alpha,
                                                        acc[mt][nt][1] * alpha);
                *(__half2*)(C + i1) = __floats2half2_rn(acc[mt][nt][2] * alpha,
                                                        acc[mt][nt][3] * alpha);
            } else {
                float* C = (float*)Cv;
                float2 v0, v1;
                v0.x = acc[mt][nt][0] * alpha;
                v0.y = acc[mt][nt][1] * alpha;
                v1.x = acc[mt][nt][2] * alpha;
                v1.y = acc[mt][nt][3] * alpha;
                if (R) {
                    const float2 r0 = *(const float2*)(R + i0);
                    const float2 r1 = *(const float2*)(R + i1);
                    v0.x += r0.x; v0.y += r0.y;
                    v1.x += r1.x; v1.y += r1.y;
                }
                *(float2*)(C + i0) = v0;
                *(float2*)(C + i1) = v1;
            }
        }
    }
}

// ---------------------------------------------------------------------------
// fp32 -> fp16 convert (elementwise, float4)
// ---------------------------------------------------------------------------
__global__ __launch_bounds__(256) void cvt_kernel(
    const float* __restrict__ x, __half* __restrict__ h, int n4)
{
    int i = blockIdx.x * 256 + threadIdx.x;
    if (i >= n4) return;
    float4 v = ((const float4*)x)[i];
    ((__half2*)h)[2 * i]     = __floats2half2_rn(v.x, v.y);
    ((__half2*)h)[2 * i + 1] = __floats2half2_rn(v.z, v.w);
}

// ---------------------------------------------------------------------------
// Transpose + convert: W (K x N fp32) -> Wt (N x K fp16)
// ---------------------------------------------------------------------------
__global__ __launch_bounds__(256) void tcvt_kernel(
    const float* __restrict__ W, __half* __restrict__ h, int K, int N)
{
    __shared__ float t[32][33];
    const int tx = threadIdx.x, ty = threadIdx.y;  // 32 x 8
    const int bn = blockIdx.x * 32;
    const int bk = blockIdx.y * 32;
#pragma unroll
    for (int r = 0; r < 4; r++)
        t[ty + r * 8][tx] = W[(size_t)(bk + ty + r * 8) * N + bn + tx];
    __syncthreads();
#pragma unroll
    for (int r = 0; r < 4; r++) {
        int row = ty + r * 8;
        h[(size_t)(bn + row) * K + bk + tx] = __float2half_rn(t[tx][row]);
    }
}

// ---------------------------------------------------------------------------
// Attention — fp16 Q + combined KV (4096-wide: K cols 0-2047, V 2048-4095).
// Per (b0+blockIdx.z, s, h) block of 128 threads; b0 selects batch chunk.
// ---------------------------------------------------------------------------
__global__ __launch_bounds__(128) void attn_kernel(
    const __half* __restrict__ qb, const __half* __restrict__ kvb,
    __half* __restrict__ ob, int b0)
{
    const int h = blockIdx.x;
    const int s = blockIdx.y;
    const int b = b0 + blockIdx.z;
    const int tid = threadIdx.x;
    const int lane = tid & 31;
    const int w = tid >> 5;

    __shared__ float sc[32];
    __shared__ float pr[32];

    const __half* qv = qb + ((size_t)(b * S_ + s) * NH_ + h) * HD_;
    float2 qraw = ((const float2*)qv)[lane];
    __half2 q01 = *(__half2*)&qraw.x;
    __half2 q23 = *(__half2*)&qraw.y;
    float2 qf0 = __half22float2(q01);
    float2 qf1 = __half22float2(q23);

    const int pprev = (s > 0) ? (s - 1) : 0;

#pragma unroll
    for (int j = 0; j < 8; j++) {
        int i = w * 8 + j;
        int p = (i < 16) ? pprev : s;
        int n = i & 15;
        const __half* kr = kvb + ((size_t)((b * S_ + p) * NN_ + h)) * 4096 + n * HD_;
        float2 kraw = ((const float2*)kr)[lane];
        __half2 k01 = *(__half2*)&kraw.x;
        __half2 k23 = *(__half2*)&kraw.y;
        float2 kf0 = __half22float2(k01);
        float2 kf1 = __half22float2(k23);
        float part = qf0.x * kf0.x + qf0.y * kf0.y + qf1.x * kf1.x + qf1.y * kf1.y;
#pragma unroll
        for (int off = 16; off; off >>= 1)
            part += __shfl_xor_sync(0xffffffffu, part, off);
        if (lane == 0) sc[i] = part;
    }
    __syncthreads();

    if (tid < 32) {
        float x = sc[tid];
        float m = x;
#pragma unroll
        for (int off = 16; off; off >>= 1)
            m = fmaxf(m, __shfl_xor_sync(0xffffffffu, m, off));
        float e = expf(x - m);
        float sum = e;
#pragma unroll
        for (int off = 16; off; off >>= 1)
            sum += __shfl_xor_sync(0xffffffffu, sum, off);
        pr[tid] = e / sum;
    }
    __syncthreads();

    float acc = 0.f;
    const int d = tid;
#pragma unroll 8
    for (int i = 0; i < 32; i++) {
        int p = (i < 16) ? pprev : s;
        int n = i & 15;
        acc += pr[i] * __half2float(
            kvb[((size_t)((b * S_ + p) * NN_ + h)) * 4096 + 2048 + n * HD_ + d]);
    }
    ob[((size_t)(b * S_ + s) * NH_ + h) * HD_ + d] = __float2half_rn(acc);
}

// ---------------------------------------------------------------------------
// Launch — batch-pipelined DAG:
//   sC: ext cvt b1 -> eCvt1
//   s2: hidden cvt -> Wq tcvt -> Q GEMM -> Wo tcvt
//       then wait eKV0 -> attn(b0) -> O GEMM(b0) -> eO0   (hides under KV_b1)
//   0:  Wk/Wv tcvt -> ext cvt b0 -> KV GEMM b0 -> eKV0
//       wait eCvt1 -> KV GEMM b1 -> attn(b1) -> O GEMM(b1) -> wait eO0
// ---------------------------------------------------------------------------
extern "C" void kernel_launch(void* const* d_in, const int* in_sizes, int n_in,
                              void* d_out, int out_size)
{
    const float* hidden = (const float*)d_in[0];  // (B,S,HID)
    const float* ext    = (const float*)d_in[1];  // (B,S,NN,RHID)
    const float* Wq     = (const float*)d_in[2];  // (HID, 2048)
    const float* Wk     = (const float*)d_in[3];  // (RHID, 2048)
    const float* Wv     = (const float*)d_in[4];  // (RHID, 2048)
    const float* Wo     = (const float*)d_in[5];  // (2048, HID)
    float* out = (float*)d_out;

    __half *qh, *kvh, *aoh, *exth, *hidh, *wqh, *wkvh, *woh;
    cudaGetSymbolAddress((void**)&qh,   g_qh);
    cudaGetSymbolAddress((void**)&kvh,  g_kvh);
    cudaGetSymbolAddress((void**)&aoh,  g_aoh);
    cudaGetSymbolAddress((void**)&exth, g_exth);
    cudaGetSymbolAddress((void**)&hidh, g_hidh);
    cudaGetSymbolAddress((void**)&wqh,  g_wqh);
    cudaGetSymbolAddress((void**)&wkvh, g_wkvh);
    cudaGetSymbolAddress((void**)&woh,  g_woh);

    cudaFuncSetAttribute(gemm_mma_kernel<true>,
                         cudaFuncAttributeMaxDynamicSharedMemorySize, GEMM_DSMEM);
    cudaFuncSetAttribute(gemm_mma_kernel<false>,
                         cudaFuncAttributeMaxDynamicSharedMemorySize, GEMM_DSMEM);

    // One-time host-object creation (no device memory).
    static cudaStream_t s2 = nullptr, sC = nullptr;
    static cudaEvent_t eFork = nullptr, eCvt1 = nullptr, eKV0 = nullptr,
                       eO0 = nullptr;
    if (s2 == nullptr) {
        cudaStreamCreateWithFlags(&s2, cudaStreamNonBlocking);
        cudaStreamCreateWithFlags(&sC, cudaStreamNonBlocking);
        cudaEventCreateWithFlags(&eFork, cudaEventDisableTiming);
        cudaEventCreateWithFlags(&eCvt1, cudaEventDisableTiming);
        cudaEventCreateWithFlags(&eKV0, cudaEventDisableTiming);
        cudaEventCreateWithFlags(&eO0, cudaEventDisableTiming);
    }

    // Batch offsets
    const size_t extHalf = (size_t)16384 * 1024;   // 16,777,216 elems
    const size_t kvHalf  = (size_t)16384 * 4096;   // rows 16384..32767
    const size_t aoHalf  = (size_t)1024 * 2048;

    cudaEventRecord(eFork, 0);
    cudaStreamWaitEvent(s2, eFork, 0);
    cudaStreamWaitEvent(sC, eFork, 0);

    // --- sC: ext convert, batch 1 ---
    cvt_kernel<<<16384, 256, 0, sC>>>(ext + extHalf, exth + extHalf, 4194304);
    cudaEventRecord(eCvt1, sC);

    // --- s2: Q chain + Wo prep ---
    cvt_kernel<<<4096, 256, 0, s2>>>(hidden, hidh, 1048576);
    tcvt_kernel<<<dim3(64, 64), dim3(32, 8), 0, s2>>>(Wq, wqh, 2048, 2048);
    gemm_mma_kernel<true><<<dim3(16, 16), 256, GEMM_DSMEM, s2>>>(
        hidh, wqh, nullptr, qh, 2048, 2048, SCALE_);
    tcvt_kernel<<<dim3(64, 64), dim3(32, 8), 0, s2>>>(Wo, woh, 2048, 2048);

    // --- main: weights, ext cvt b0, KV GEMM b0 ---
    tcvt_kernel<<<dim3(64, 32), dim3(32, 8)>>>(Wk, wkvh, 1024, 2048);
    tcvt_kernel<<<dim3(64, 32), dim3(32, 8)>>>(Wv, wkvh + (size_t)2048 * 1024,
                                               1024, 2048);
    cvt_kernel<<<16384, 256>>>(ext, exth, 4194304);
    gemm_mma_kernel<true><<<dim3(32, 128), 256, GEMM_DSMEM>>>(
        exth, wkvh, nullptr, kvh, 1024, 4096, 1.0f);
    cudaEventRecord(eKV0, 0);

    // --- s2: batch-0 tail hides under KV GEMM b1 ---
    cudaStreamWaitEvent(s2, eKV0, 0);
    attn_kernel<<<dim3(NH_, S_, 1), dim3(128), 0, s2>>>(qh, kvh, aoh, 0);
    gemm_mma_kernel<false><<<dim3(16, 8), 256, GEMM_DSMEM, s2>>>(
        aoh, woh, hidden, out, 2048, 2048, 1.0f);
    cudaEventRecord(eO0, s2);

    // --- main: KV GEMM b1, batch-1 tail ---
    cudaStreamWaitEvent(0, eCvt1, 0);
    gemm_mma_kernel<true><<<dim3(32, 128), 256, GEMM_DSMEM>>>(
        exth + extHalf, wkvh, nullptr, kvh + kvHalf, 1024, 4096, 1.0f);
    attn_kernel<<<dim3(NH_, S_, 1), dim3(128)>>>(qh, kvh, aoh, 1);
    gemm_mma_kernel<false><<<dim3(16, 8), 256, GEMM_DSMEM>>>(
        aoh + aoHalf, woh, hidden + aoHalf, out + aoHalf, 2048, 2048, 1.0f);

    // join s2 back into the origin stream before returning
    cudaStreamWaitEvent(0, eO0, 0);
}